// round 15
// baseline (speedup 1.0000x reference)
#include <cuda_runtime.h>
#include <cstdint>
#include <math.h>

#define B_ 2
#define S_ 2048
#define H_ 1024
#define NH_ 16
#define HD_ 64
#define H3_ 3072
#define R_ 4096   // B*S

// ---- scratch (static device globals; no runtime allocation) ----
__device__ __align__(256) float g_mod[B_ * H3_];           // [B, 3H] (scale|shift|gate)
__device__ __align__(256) float g_h[(size_t)R_ * H_];      // modulated LN output (tf32-rounded)
__device__ __align__(256) float g_qkv[(size_t)R_ * H3_];   // qkv projections (tf32-rounded)
__device__ __align__(256) float g_o[(size_t)R_ * H_];      // attention output (tf32-rounded)
__device__ __align__(256) float g_w1[(size_t)H3_ * H_];    // tf32-rounded w_qkv
__device__ __align__(256) float g_w2[(size_t)H_ * H_];     // tf32-rounded w_o

// ============================================================
// helpers
// ============================================================
__device__ __forceinline__ float warp_sum(float v) {
#pragma unroll
    for (int o = 16; o; o >>= 1) v += __shfl_xor_sync(0xffffffffu, v, o);
    return v;
}

__device__ __forceinline__ float to_tf32(float x) {
    float r;
    asm("cvt.rna.tf32.f32 %0, %1;" : "=f"(r) : "f"(x));
    return r;
}

__device__ __forceinline__ uint32_t cvta_smem(const void* p) {
    uint32_t a;
    asm("{ .reg .u64 t; cvta.to.shared.u64 t, %1; cvt.u32.u64 %0, t; }" : "=r"(a) : "l"(p));
    return a;
}

__device__ __forceinline__ void cp_async16(uint32_t dst, const void* src) {
    asm volatile("cp.async.cg.shared.global [%0], [%1], 16;" :: "r"(dst), "l"(src));
}

// mma.sync tf32: D[16x8] += A[16x8] * B[8x8]   (portable, sm_80+)
__device__ __forceinline__ void mma1688(float* d, const uint32_t* a, uint32_t b0, uint32_t b1) {
    asm volatile(
        "mma.sync.aligned.m16n8k8.row.col.f32.tf32.tf32.f32 "
        "{%0,%1,%2,%3}, {%4,%5,%6,%7}, {%8,%9}, {%0,%1,%2,%3};"
        : "+f"(d[0]), "+f"(d[1]), "+f"(d[2]), "+f"(d[3])
        : "r"(a[0]), "r"(a[1]), "r"(a[2]), "r"(a[3]), "r"(b0), "r"(b1));
}

// ldmatrix x4: four m8n8 b16 matrices (lane i supplies row addr for matrix i/8)
__device__ __forceinline__ void ldsm4(uint32_t* r, uint32_t addr) {
    asm volatile("ldmatrix.sync.aligned.m8n8.x4.shared.b16 {%0,%1,%2,%3}, [%4];"
                 : "=r"(r[0]), "=r"(r[1]), "=r"(r[2]), "=r"(r[3]) : "r"(addr));
}

// ============================================================
// 0) round weights fp32 -> tf32 (RNA)
// ============================================================
__global__ void __launch_bounds__(256) round_w_kernel(const float* __restrict__ wq,
                                                      const float* __restrict__ wo) {
    const size_t n1 = (size_t)H3_ * H_ / 4;
    const size_t n2 = (size_t)H_ * H_ / 4;
    size_t i = (size_t)blockIdx.x * 256 + threadIdx.x;
    if (i < n1) {
        float4 v = ((const float4*)wq)[i];
        v.x = to_tf32(v.x); v.y = to_tf32(v.y); v.z = to_tf32(v.z); v.w = to_tf32(v.w);
        ((float4*)g_w1)[i] = v;
    } else if (i < n1 + n2) {
        size_t j = i - n1;
        float4 v = ((const float4*)wo)[j];
        v.x = to_tf32(v.x); v.y = to_tf32(v.y); v.z = to_tf32(v.z); v.w = to_tf32(v.w);
        ((float4*)g_w2)[j] = v;
    }
}

// ============================================================
// 1) mod = silu(ada) @ mod_w^T + mod_b       (one warp per output)
// ============================================================
__global__ void __launch_bounds__(256) mod_kernel(const float* __restrict__ ada,
                                                  const float* __restrict__ mw,
                                                  const float* __restrict__ mb) {
    int gw = (blockIdx.x * 256 + threadIdx.x) >> 5;
    int lane = threadIdx.x & 31;
    int b = gw / H3_, j = gw % H3_;
    const float* ar = ada + b * 1024;
    const float* wr = mw + (size_t)j * 1024;
    float acc = 0.f;
#pragma unroll 4
    for (int a = lane; a < 1024; a += 32) {
        float v = ar[a];
        float s = v / (1.f + __expf(-v));
        acc = fmaf(s, wr[a], acc);
    }
    acc = warp_sum(acc);
    if (lane == 0) g_mod[gw] = acc + mb[j];
}

// ============================================================
// 2) h = LN(x)*ln_w*(scale+1) + shift   (tf32-rounded for GEMM A)
// ============================================================
__global__ void __launch_bounds__(256) ln_mod_kernel(const float* __restrict__ x,
                                                     const float* __restrict__ ln_w) {
    int row = blockIdx.x;
    int tid = threadIdx.x;
    int b = row >> 11;

    float4 xv = ((const float4*)x)[(size_t)row * 256 + tid];
    float sum = xv.x + xv.y + xv.z + xv.w;
    float sq  = xv.x * xv.x + xv.y * xv.y + xv.z * xv.z + xv.w * xv.w;
    sum = warp_sum(sum);
    sq  = warp_sum(sq);

    __shared__ float rs[8], rq[8], mv[2];
    int warp = tid >> 5, lane = tid & 31;
    if (lane == 0) { rs[warp] = sum; rq[warp] = sq; }
    __syncthreads();
    if (tid == 0) {
        float s = 0.f, q = 0.f;
#pragma unroll
        for (int w = 0; w < 8; ++w) { s += rs[w]; q += rq[w]; }
        float mean = s * (1.f / 1024.f);
        float var  = q * (1.f / 1024.f) - mean * mean;
        mv[0] = mean;
        mv[1] = rsqrtf(var + 1e-5f);
    }
    __syncthreads();
    float mean = mv[0], rstd = mv[1];

    float4 lw = ((const float4*)ln_w)[tid];
    const float* mp = g_mod + b * H3_;
    float4 sc = ((const float4*)mp)[tid];
    float4 sh = ((const float4*)(mp + H_))[tid];

    float4 h;
    h.x = to_tf32((xv.x - mean) * rstd * lw.x * (sc.x + 1.f) + sh.x);
    h.y = to_tf32((xv.y - mean) * rstd * lw.y * (sc.y + 1.f) + sh.y);
    h.z = to_tf32((xv.z - mean) * rstd * lw.z * (sc.z + 1.f) + sh.z);
    h.w = to_tf32((xv.w - mean) * rstd * lw.w * (sc.w + 1.f) + sh.w);
    ((float4*)g_h)[(size_t)row * 256 + tid] = h;
}

// ============================================================
// 3/6) tf32 mma.sync GEMM NT: C[M,N] = A[M,1024] * B[N,1024]^T
//      128x128 CTA tile, BK=16, 4-stage cp.async, 8 warps (32x64 each).
//      Single barrier per k-iter: wait -> sync -> issue load(it+3) -> MMAs.
// ============================================================
#define GK_ 1024
#define GNIT 64                 // GK_/16
#define STG_FLOATS 5120         // per stage: A(2560) + B(2560)
#define STG_BYTES  20480

__device__ __forceinline__ void gemm_load_stage(uint32_t sb, const float* A, const float* Bm,
                                                int row0, int col0, int it, int tid) {
    int s = it & 3;
    int krow = it * 16;
    int r = tid >> 1;                 // 0..127
    int off = (tid & 1) * 8;          // 0 or 8 floats
    uint32_t base = sb + s * STG_BYTES;
    const float* ga = A + (size_t)(row0 + r) * GK_ + krow + off;
    uint32_t da = base + (r * 20 + off) * 4;
    cp_async16(da, ga);
    cp_async16(da + 16, ga + 4);
    const float* gb = Bm + (size_t)(col0 + r) * GK_ + krow + off;
    uint32_t db = base + 10240 + (r * 20 + off) * 4;   // B tile: +10240 bytes
    cp_async16(db, gb);
    cp_async16(db + 16, gb + 4);
    asm volatile("cp.async.commit_group;" ::: "memory");
}

__global__ void __launch_bounds__(256, 2) tc_gemm(float* __restrict__ Cext, int N, int mode) {
    extern __shared__ float sm[];
    const float* A  = mode ? g_o : g_h;
    const float* Bm = mode ? g_w2 : g_w1;
    float* C = mode ? Cext : g_qkv;

    uint32_t sb = cvta_smem(sm);
    int tid = threadIdx.x;
    int wid = tid >> 5, lane = tid & 31;
    int warp_m = wid & 3, warp_n = wid >> 2;
    int row0 = blockIdx.y << 7, col0 = blockIdx.x << 7;

    int sub = lane & 7, mi = lane >> 3;
    // A-frag: m0..m3 = (rows+0,k+0),(rows+8,k+0),(rows+0,k+4),(rows+8,k+4)
    uint32_t a_off = ((uint32_t)(((mi & 1) * 8 + sub) * 20 + (mi >> 1) * 4)) * 4;
    // B-frag pair (nt, nt+1): m0..m3 = (nt,k0),(nt,k4),(nt+1,k0),(nt+1,k4)
    uint32_t b_off = 10240u + ((uint32_t)(((mi >> 1) * 8 + sub) * 20 + (mi & 1) * 4)) * 4;

    float acc[2][8][4];
#pragma unroll
    for (int i = 0; i < 2; ++i)
#pragma unroll
        for (int j = 0; j < 8; ++j)
#pragma unroll
            for (int q = 0; q < 4; ++q) acc[i][j][q] = 0.f;

    gemm_load_stage(sb, A, Bm, row0, col0, 0, tid);
    gemm_load_stage(sb, A, Bm, row0, col0, 1, tid);
    gemm_load_stage(sb, A, Bm, row0, col0, 2, tid);

    for (int it = 0; it < GNIT; ++it) {
        asm volatile("cp.async.wait_group 2;" ::: "memory");   // stage it resident
        __syncthreads();   // all warps see stage it; all done reading stage (it+3)&3
        if (it + 3 < GNIT) gemm_load_stage(sb, A, Bm, row0, col0, it + 3, tid);

        uint32_t st = sb + (it & 3) * STG_BYTES;
#pragma unroll
        for (int k8 = 0; k8 < 16; k8 += 8) {
            uint32_t a0[4], a1[4];
            ldsm4(a0, st + a_off + (uint32_t)((warp_m * 32) * 20 + k8) * 4);
            ldsm4(a1, st + a_off + (uint32_t)((warp_m * 32 + 16) * 20 + k8) * 4);
#pragma unroll
            for (int ntp = 0; ntp < 4; ++ntp) {
                uint32_t bb[4];
                ldsm4(bb, st + b_off + (uint32_t)((warp_n * 64 + ntp * 16) * 20 + k8) * 4);
                mma1688(acc[0][2 * ntp],     a0, bb[0], bb[1]);
                mma1688(acc[1][2 * ntp],     a1, bb[0], bb[1]);
                mma1688(acc[0][2 * ntp + 1], a0, bb[2], bb[3]);
                mma1688(acc[1][2 * ntp + 1], a1, bb[2], bb[3]);
            }
        }
    }

    int lr = lane >> 2, lk = lane & 3;
    // epilogue (mode 0: round to tf32 for attention consumers; mode 1: gate)
#pragma unroll
    for (int mt = 0; mt < 2; ++mt) {
        int r = row0 + warp_m * 32 + mt * 16 + lr;
        int gb = (r >> 11) * H3_ + 2 * H_;
#pragma unroll
        for (int nt = 0; nt < 8; ++nt) {
            int c = col0 + warp_n * 64 + nt * 8 + lk * 2;
            float2 v0 = make_float2(acc[mt][nt][0], acc[mt][nt][1]);
            float2 v1 = make_float2(acc[mt][nt][2], acc[mt][nt][3]);
            if (mode) {
                float gx = g_mod[gb + c], gy = g_mod[gb + c + 1];
                v0.x *= gx; v0.y *= gy;
                v1.x *= gx; v1.y *= gy;
            } else {
                v0.x = to_tf32(v0.x); v0.y = to_tf32(v0.y);
                v1.x = to_tf32(v1.x); v1.y = to_tf32(v1.y);
            }
            *(float2*)(C + (size_t)r * N + c) = v0;
            *(float2*)(C + (size_t)(r + 8) * N + c) = v1;
        }
    }
}

// ============================================================
// 4) per-head QK layernorm + RoPE, in place on g_qkv
//    q gets 0.125*log2(e) folded in (softmax uses exp2); outputs tf32-rounded
// ============================================================
__global__ void __launch_bounds__(256) qknorm_rope_kernel(const float* __restrict__ freqs,
                                                          const float* __restrict__ qn_w,
                                                          const float* __restrict__ kn_w) {
    int row = blockIdx.x;
    int s = row & (S_ - 1);
    int warp = threadIdx.x >> 5;
    int lane = threadIdx.x & 31;

    float f0 = freqs[(s * 32 + lane) * 2 + 0];
    float f1 = freqs[(s * 32 + lane) * 2 + 1];

    for (int task = warp; task < 32; task += 8) {
        int type = task >> 4;
        int head = task & 15;
        size_t base = (size_t)row * H3_ + type * H_ + head * HD_;
        float v0 = g_qkv[base + lane * 2];
        float v1 = g_qkv[base + lane * 2 + 1];
        float sum = warp_sum(v0 + v1);
        float sq  = warp_sum(v0 * v0 + v1 * v1);
        float mean = sum * (1.f / 64.f);
        float var  = sq * (1.f / 64.f) - mean * mean;
        float rstd = rsqrtf(var + 1e-5f);
        const float* w = type ? kn_w : qn_w;
        float n0 = (v0 - mean) * rstd * w[lane * 2];
        float n1 = (v1 - mean) * rstd * w[lane * 2 + 1];
        float r0 = n0 * f0 - n1 * f1;
        float r1 = n1 * f0 + n0 * f1;
        float qs = type ? 1.f : (0.125f * 1.44269504088896340736f);
        g_qkv[base + lane * 2]     = to_tf32(r0 * qs);
        g_qkv[base + lane * 2 + 1] = to_tf32(r1 * qs);
    }
}

// ============================================================
// 5) flash attention (non-causal), tf32 mma.sync + ldmatrix, base-2 softmax
//    grid = (S/128, B*NH), 256 threads (8 warps x m16 q-rows)
// ============================================================
#define KS_ 68
#define VS_ 72
#define VT_S 68
#define PS_ 68
#define OFF_VB (2 * 64 * KS_)            // 8704
#define OFF_VT (OFF_VB + 2 * 64 * VS_)   // 17920
#define OFF_P  (OFF_VT + 64 * VT_S)      // 22272
#define ATT_SMEM ((OFF_P + 8 * 16 * PS_) * 4)   // 123904 bytes

__device__ __forceinline__ void attn_load_kv(uint32_t sb, const float* gkv, int t, int tid) {
    int s = t & 1;
    int r = tid >> 2;                 // 0..63 (key within tile)
    int cc = (tid & 3) * 16;          // dim chunk
    const float* kg = gkv + (size_t)(t * 64 + r) * H3_ + cc;
    const float* vg = kg + H_;
    uint32_t kd = sb + (uint32_t)(s * 64 * KS_ + r * KS_ + cc) * 4;
    uint32_t vd = sb + (uint32_t)(OFF_VB + s * 64 * VS_ + r * VS_ + cc) * 4;
#pragma unroll
    for (int i = 0; i < 4; ++i) {
        cp_async16(kd + i * 16, kg + i * 4);
        cp_async16(vd + i * 16, vg + i * 4);
    }
    asm volatile("cp.async.commit_group;" ::: "memory");
}

__global__ void __launch_bounds__(256, 1) attn_mma_kernel() {
    extern __shared__ float sm[];
    uint32_t sb = cvta_smem(sm);

    int tid = threadIdx.x, wid = tid >> 5, lane = tid & 31;
    int lr = lane >> 2, lk = lane & 3;
    int sub = lane & 7, mi = lane >> 3;
    int q0 = blockIdx.x << 7;
    int b = blockIdx.y >> 4, head = blockIdx.y & 15;

    const float* gkv = g_qkv + (size_t)b * S_ * H3_ + H_ + head * HD_;  // K base (V = +H_)

    // per-lane LDSM offsets (bytes)
    uint32_t k_loff = (uint32_t)(sub * KS_ + (mi >> 1) * 8 + (mi & 1) * 4) * 4;
    uint32_t vt_loff = (uint32_t)(((mi >> 1) * 8 + sub) * VT_S + (mi & 1) * 4) * 4;
    uint32_t p_loff = (uint32_t)(((mi & 1) * 8 + sub) * PS_ + (mi >> 1) * 4) * 4;

    // Q fragments (registers for the whole kernel; pre-scaled & tf32)
    uint32_t qa[8][4];
    {
        const float* Qb = g_qkv + (size_t)(b * S_ + q0 + wid * 16) * H3_ + head * HD_;
#pragma unroll
        for (int ks = 0; ks < 8; ++ks) {
            qa[ks][0] = __float_as_uint(Qb[(size_t)lr * H3_ + ks * 8 + lk]);
            qa[ks][1] = __float_as_uint(Qb[(size_t)(lr + 8) * H3_ + ks * 8 + lk]);
            qa[ks][2] = __float_as_uint(Qb[(size_t)lr * H3_ + ks * 8 + lk + 4]);
            qa[ks][3] = __float_as_uint(Qb[(size_t)(lr + 8) * H3_ + ks * 8 + lk + 4]);
        }
    }

    float m0 = -1e30f, m1 = -1e30f, l0 = 0.f, l1 = 0.f;
    float o[8][4];
#pragma unroll
    for (int nt = 0; nt < 8; ++nt)
#pragma unroll
        for (int q = 0; q < 4; ++q) o[nt][q] = 0.f;

    float* Pw = sm + OFF_P + wid * 16 * PS_;
    uint32_t Pwb = sb + (uint32_t)(OFF_P + wid * 16 * PS_) * 4;
    uint32_t VTb = sb + (uint32_t)OFF_VT * 4;

    attn_load_kv(sb, gkv, 0, tid);

    for (int t = 0; t < 32; ++t) {
        asm volatile("cp.async.wait_group 0;" ::: "memory");   // tile t resident
        __syncthreads();   // visible to all; prev iter's reads of buffer (t+1)&1 done
        if (t < 31) attn_load_kv(sb, gkv, t + 1, tid);

        // ---- transpose V tile: Vbuf[key][dim] -> VT[dim][key] ----
        {
            int key = tid & 63, dbase = (tid >> 6) * 16;
            const float* src = sm + OFF_VB + (t & 1) * 64 * VS_ + key * VS_ + dbase;
            float4 va = ((const float4*)src)[0];
            float4 vb4 = ((const float4*)src)[1];
            float4 vc = ((const float4*)src)[2];
            float4 vd = ((const float4*)src)[3];
            float vv[16] = {va.x, va.y, va.z, va.w, vb4.x, vb4.y, vb4.z, vb4.w,
                            vc.x, vc.y, vc.z, vc.w, vd.x, vd.y, vd.z, vd.w};
            float* vt = sm + OFF_VT;
#pragma unroll
            for (int d = 0; d < 16; ++d) vt[(dbase + d) * VT_S + key] = vv[d];
        }

        uint32_t Kst = sb + (uint32_t)((t & 1) * 64 * KS_) * 4;

        // ---- scores = Q @ K^T (pre-scaled, base-2 domain) ----
        float sc[8][4];
#pragma unroll
        for (int nt = 0; nt < 8; ++nt) {
            uint32_t kb[16];
#pragma unroll
            for (int p = 0; p < 4; ++p)
                ldsm4(kb + 4 * p, Kst + k_loff + (uint32_t)(nt * 8 * KS_ + p * 16) * 4);
#pragma unroll
            for (int q = 0; q < 4; ++q) sc[nt][q] = 0.f;
#pragma unroll
            for (int ks = 0; ks < 8; ++ks)
                mma1688(sc[nt], qa[ks], kb[2 * ks], kb[2 * ks + 1]);
        }

        // ---- online softmax, base 2 (rows lr, lr+8; quad lanes share a row) ----
        float tm0 = -1e30f, tm1 = -1e30f;
#pragma unroll
        for (int nt = 0; nt < 8; ++nt) {
            tm0 = fmaxf(tm0, fmaxf(sc[nt][0], sc[nt][1]));
            tm1 = fmaxf(tm1, fmaxf(sc[nt][2], sc[nt][3]));
        }
        tm0 = fmaxf(tm0, __shfl_xor_sync(0xffffffffu, tm0, 1));
        tm0 = fmaxf(tm0, __shfl_xor_sync(0xffffffffu, tm0, 2));
        tm1 = fmaxf(tm1, __shfl_xor_sync(0xffffffffu, tm1, 1));
        tm1 = fmaxf(tm1, __shfl_xor_sync(0xffffffffu, tm1, 2));
        float nm0 = fmaxf(m0, tm0), nm1 = fmaxf(m1, tm1);
        float a0 = exp2f(m0 - nm0), a1 = exp2f(m1 - nm1);
        m0 = nm0; m1 = nm1;

        float rs0 = 0.f, rs1 = 0.f;
#pragma unroll
        for (int nt = 0; nt < 8; ++nt) {
            float p0 = exp2f(sc[nt][0] - nm0);
            float p1 = exp2f(sc[nt][1] - nm0);
            float p2 = exp2f(sc[nt][2] - nm1);
            float p3 = exp2f(sc[nt][3] - nm1);
            rs0 += p0 + p1;
            rs1 += p2 + p3;
            *(float2*)(Pw + lr * PS_ + nt * 8 + lk * 2) =
                make_float2(to_tf32(p0), to_tf32(p1));
            *(float2*)(Pw + (lr + 8) * PS_ + nt * 8 + lk * 2) =
                make_float2(to_tf32(p2), to_tf32(p3));
        }
        rs0 += __shfl_xor_sync(0xffffffffu, rs0, 1);
        rs0 += __shfl_xor_sync(0xffffffffu, rs0, 2);
        rs1 += __shfl_xor_sync(0xffffffffu, rs1, 1);
        rs1 += __shfl_xor_sync(0xffffffffu, rs1, 2);
        l0 = l0 * a0 + rs0;
        l1 = l1 * a1 + rs1;
#pragma unroll
        for (int nt = 0; nt < 8; ++nt) {
            o[nt][0] *= a0; o[nt][1] *= a0;
            o[nt][2] *= a1; o[nt][3] *= a1;
        }
        __syncthreads();   // VT transposed + visible

        // ---- O += P @ V  (P A-frags + VT B-frags via LDSM) ----
#pragma unroll
        for (int ks = 0; ks < 8; ++ks) {
            uint32_t pa[4];
            ldsm4(pa, Pwb + p_loff + (uint32_t)(ks * 8) * 4);
#pragma unroll
            for (int ntp = 0; ntp < 4; ++ntp) {
                uint32_t vb[4];
                ldsm4(vb, VTb + vt_loff + (uint32_t)(ntp * 16 * VT_S + ks * 8) * 4);
                mma1688(o[2 * ntp],     pa, vb[0], vb[1]);
                mma1688(o[2 * ntp + 1], pa, vb[2], vb[3]);
            }
        }
    }

    float inv0 = 1.f / l0, inv1 = 1.f / l1;
    int r = b * S_ + q0 + wid * 16 + lr;
    float* ob = g_o + (size_t)r * H_ + head * HD_;
#pragma unroll
    for (int nt = 0; nt < 8; ++nt) {
        *(float2*)(ob + nt * 8 + lk * 2) =
            make_float2(to_tf32(o[nt][0] * inv0), to_tf32(o[nt][1] * inv0));
        *(float2*)(ob + (size_t)8 * H_ + nt * 8 + lk * 2) =
            make_float2(to_tf32(o[nt][2] * inv1), to_tf32(o[nt][3] * inv1));
    }
}

// ============================================================
extern "C" void kernel_launch(void* const* d_in, const int* in_sizes, int n_in,
                              void* d_out, int out_size) {
    (void)in_sizes; (void)n_in; (void)out_size;
    const float* x     = (const float*)d_in[0];
    const float* ada   = (const float*)d_in[1];
    const float* freqs = (const float*)d_in[2];
    const float* w_qkv = (const float*)d_in[3];
    const float* w_o   = (const float*)d_in[4];
    const float* ln_w  = (const float*)d_in[5];
    const float* mod_w = (const float*)d_in[6];
    const float* mod_b = (const float*)d_in[7];
    const float* qn_w  = (const float*)d_in[8];
    const float* kn_w  = (const float*)d_in[9];
    float* out = (float*)d_out;

    const int SMEM_DYN = 4 * STG_BYTES;   // 81920 bytes
    cudaFuncSetAttribute(tc_gemm, cudaFuncAttributeMaxDynamicSharedMemorySize, SMEM_DYN);
    cudaFuncSetAttribute(attn_mma_kernel, cudaFuncAttributeMaxDynamicSharedMemorySize, ATT_SMEM);

    mod_kernel<<<768, 256>>>(ada, mod_w, mod_b);
    round_w_kernel<<<4096, 256>>>(w_qkv, w_o);
    ln_mod_kernel<<<R_, 256>>>(x, ln_w);
    tc_gemm<<<dim3(H3_ / 128, R_ / 128), 256, SMEM_DYN>>>(nullptr, H3_, 0);
    qknorm_rope_kernel<<<R_, 256>>>(freqs, qn_w, kn_w);
    attn_mma_kernel<<<dim3(S_ / 128, B_ * NH_), 256, ATT_SMEM>>>();
    tc_gemm<<<dim3(H_ / 128, R_ / 128), 256, SMEM_DYN>>>(out, H_, 1);
}

// round 16
// speedup vs baseline: 1.0015x; 1.0015x over previous
#include <cuda_runtime.h>
#include <cstdint>
#include <math.h>

#define B_ 2
#define S_ 2048
#define H_ 1024
#define NH_ 16
#define HD_ 64
#define H3_ 3072
#define R_ 4096   // B*S

// ---- scratch (static device globals; no runtime allocation) ----
__device__ __align__(256) float g_mod[B_ * H3_];           // [B, 3H] (scale|shift|gate)
__device__ __align__(256) float g_h[(size_t)R_ * H_];      // modulated LN output (tf32-rounded)
__device__ __align__(256) float g_qkv[(size_t)R_ * H3_];   // qkv projections (tf32-rounded)
__device__ __align__(256) float g_o[(size_t)R_ * H_];      // attention output (tf32-rounded)
__device__ __align__(256) float g_w1[(size_t)H3_ * H_];    // tf32-rounded w_qkv
__device__ __align__(256) float g_w2[(size_t)H_ * H_];     // tf32-rounded w_o

// ============================================================
// helpers
// ============================================================
__device__ __forceinline__ float warp_sum(float v) {
#pragma unroll
    for (int o = 16; o; o >>= 1) v += __shfl_xor_sync(0xffffffffu, v, o);
    return v;
}

__device__ __forceinline__ float to_tf32(float x) {
    float r;
    asm("cvt.rna.tf32.f32 %0, %1;" : "=f"(r) : "f"(x));
    return r;
}

__device__ __forceinline__ uint32_t cvta_smem(const void* p) {
    uint32_t a;
    asm("{ .reg .u64 t; cvta.to.shared.u64 t, %1; cvt.u32.u64 %0, t; }" : "=r"(a) : "l"(p));
    return a;
}

__device__ __forceinline__ void cp_async16(uint32_t dst, const void* src) {
    asm volatile("cp.async.cg.shared.global [%0], [%1], 16;" :: "r"(dst), "l"(src));
}

// mma.sync tf32: D[16x8] += A[16x8] * B[8x8]   (portable, sm_80+)
__device__ __forceinline__ void mma1688(float* d, const uint32_t* a, uint32_t b0, uint32_t b1) {
    asm volatile(
        "mma.sync.aligned.m16n8k8.row.col.f32.tf32.tf32.f32 "
        "{%0,%1,%2,%3}, {%4,%5,%6,%7}, {%8,%9}, {%0,%1,%2,%3};"
        : "+f"(d[0]), "+f"(d[1]), "+f"(d[2]), "+f"(d[3])
        : "r"(a[0]), "r"(a[1]), "r"(a[2]), "r"(a[3]), "r"(b0), "r"(b1));
}

// ldmatrix x4: four m8n8 b16 matrices (lane i supplies row addr for matrix i/8)
__device__ __forceinline__ void ldsm4(uint32_t* r, uint32_t addr) {
    asm volatile("ldmatrix.sync.aligned.m8n8.x4.shared.b16 {%0,%1,%2,%3}, [%4];"
                 : "=r"(r[0]), "=r"(r[1]), "=r"(r[2]), "=r"(r[3]) : "r"(addr));
}

// ============================================================
// 0) round weights fp32 -> tf32 (RNA)
// ============================================================
__global__ void __launch_bounds__(256) round_w_kernel(const float* __restrict__ wq,
                                                      const float* __restrict__ wo) {
    const size_t n1 = (size_t)H3_ * H_ / 4;
    const size_t n2 = (size_t)H_ * H_ / 4;
    size_t i = (size_t)blockIdx.x * 256 + threadIdx.x;
    if (i < n1) {
        float4 v = ((const float4*)wq)[i];
        v.x = to_tf32(v.x); v.y = to_tf32(v.y); v.z = to_tf32(v.z); v.w = to_tf32(v.w);
        ((float4*)g_w1)[i] = v;
    } else if (i < n1 + n2) {
        size_t j = i - n1;
        float4 v = ((const float4*)wo)[j];
        v.x = to_tf32(v.x); v.y = to_tf32(v.y); v.z = to_tf32(v.z); v.w = to_tf32(v.w);
        ((float4*)g_w2)[j] = v;
    }
}

// ============================================================
// 1) mod = silu(ada) @ mod_w^T + mod_b       (one warp per output)
// ============================================================
__global__ void __launch_bounds__(256) mod_kernel(const float* __restrict__ ada,
                                                  const float* __restrict__ mw,
                                                  const float* __restrict__ mb) {
    int gw = (blockIdx.x * 256 + threadIdx.x) >> 5;
    int lane = threadIdx.x & 31;
    int b = gw / H3_, j = gw % H3_;
    const float* ar = ada + b * 1024;
    const float* wr = mw + (size_t)j * 1024;
    float acc = 0.f;
#pragma unroll 4
    for (int a = lane; a < 1024; a += 32) {
        float v = ar[a];
        float s = v / (1.f + __expf(-v));
        acc = fmaf(s, wr[a], acc);
    }
    acc = warp_sum(acc);
    if (lane == 0) g_mod[gw] = acc + mb[j];
}

// ============================================================
// 2) h = LN(x)*ln_w*(scale+1) + shift   (tf32-rounded for GEMM A)
// ============================================================
__global__ void __launch_bounds__(256) ln_mod_kernel(const float* __restrict__ x,
                                                     const float* __restrict__ ln_w) {
    int row = blockIdx.x;
    int tid = threadIdx.x;
    int b = row >> 11;

    float4 xv = ((const float4*)x)[(size_t)row * 256 + tid];
    float sum = xv.x + xv.y + xv.z + xv.w;
    float sq  = xv.x * xv.x + xv.y * xv.y + xv.z * xv.z + xv.w * xv.w;
    sum = warp_sum(sum);
    sq  = warp_sum(sq);

    __shared__ float rs[8], rq[8], mv[2];
    int warp = tid >> 5, lane = tid & 31;
    if (lane == 0) { rs[warp] = sum; rq[warp] = sq; }
    __syncthreads();
    if (tid == 0) {
        float s = 0.f, q = 0.f;
#pragma unroll
        for (int w = 0; w < 8; ++w) { s += rs[w]; q += rq[w]; }
        float mean = s * (1.f / 1024.f);
        float var  = q * (1.f / 1024.f) - mean * mean;
        mv[0] = mean;
        mv[1] = rsqrtf(var + 1e-5f);
    }
    __syncthreads();
    float mean = mv[0], rstd = mv[1];

    float4 lw = ((const float4*)ln_w)[tid];
    const float* mp = g_mod + b * H3_;
    float4 sc = ((const float4*)mp)[tid];
    float4 sh = ((const float4*)(mp + H_))[tid];

    float4 h;
    h.x = to_tf32((xv.x - mean) * rstd * lw.x * (sc.x + 1.f) + sh.x);
    h.y = to_tf32((xv.y - mean) * rstd * lw.y * (sc.y + 1.f) + sh.y);
    h.z = to_tf32((xv.z - mean) * rstd * lw.z * (sc.z + 1.f) + sh.z);
    h.w = to_tf32((xv.w - mean) * rstd * lw.w * (sc.w + 1.f) + sh.w);
    ((float4*)g_h)[(size_t)row * 256 + tid] = h;
}

// ============================================================
// 3/6) tf32 mma.sync GEMM NT: C[M,N] = A[M,1024] * B[N,1024]^T
//      128x128 CTA tile, BK=16, 4-stage cp.async, 8 warps (32x64 each).
//      Single barrier per k-iter: wait -> sync -> issue load(it+3) -> MMAs.
// ============================================================
#define GK_ 1024
#define GNIT 64                 // GK_/16
#define STG_FLOATS 5120         // per stage: A(2560) + B(2560)
#define STG_BYTES  20480

__device__ __forceinline__ void gemm_load_stage(uint32_t sb, const float* A, const float* Bm,
                                                int row0, int col0, int it, int tid) {
    int s = it & 3;
    int krow = it * 16;
    int r = tid >> 1;                 // 0..127
    int off = (tid & 1) * 8;          // 0 or 8 floats
    uint32_t base = sb + s * STG_BYTES;
    const float* ga = A + (size_t)(row0 + r) * GK_ + krow + off;
    uint32_t da = base + (r * 20 + off) * 4;
    cp_async16(da, ga);
    cp_async16(da + 16, ga + 4);
    const float* gb = Bm + (size_t)(col0 + r) * GK_ + krow + off;
    uint32_t db = base + 10240 + (r * 20 + off) * 4;   // B tile: +10240 bytes
    cp_async16(db, gb);
    cp_async16(db + 16, gb + 4);
    asm volatile("cp.async.commit_group;" ::: "memory");
}

__global__ void __launch_bounds__(256, 2) tc_gemm(float* __restrict__ Cext, int N, int mode) {
    extern __shared__ float sm[];
    const float* A  = mode ? g_o : g_h;
    const float* Bm = mode ? g_w2 : g_w1;
    float* C = mode ? Cext : g_qkv;

    uint32_t sb = cvta_smem(sm);
    int tid = threadIdx.x;
    int wid = tid >> 5, lane = tid & 31;
    int warp_m = wid & 3, warp_n = wid >> 2;
    int row0 = blockIdx.y << 7, col0 = blockIdx.x << 7;

    int sub = lane & 7, mi = lane >> 3;
    // A-frag: m0..m3 = (rows+0,k+0),(rows+8,k+0),(rows+0,k+4),(rows+8,k+4)
    uint32_t a_off = ((uint32_t)(((mi & 1) * 8 + sub) * 20 + (mi >> 1) * 4)) * 4;
    // B-frag pair (nt, nt+1): m0..m3 = (nt,k0),(nt,k4),(nt+1,k0),(nt+1,k4)
    uint32_t b_off = 10240u + ((uint32_t)(((mi >> 1) * 8 + sub) * 20 + (mi & 1) * 4)) * 4;

    float acc[2][8][4];
#pragma unroll
    for (int i = 0; i < 2; ++i)
#pragma unroll
        for (int j = 0; j < 8; ++j)
#pragma unroll
            for (int q = 0; q < 4; ++q) acc[i][j][q] = 0.f;

    gemm_load_stage(sb, A, Bm, row0, col0, 0, tid);
    gemm_load_stage(sb, A, Bm, row0, col0, 1, tid);
    gemm_load_stage(sb, A, Bm, row0, col0, 2, tid);

    for (int it = 0; it < GNIT; ++it) {
        asm volatile("cp.async.wait_group 2;" ::: "memory");   // stage it resident
        __syncthreads();   // all warps see stage it; all done reading stage (it+3)&3
        if (it + 3 < GNIT) gemm_load_stage(sb, A, Bm, row0, col0, it + 3, tid);

        uint32_t st = sb + (it & 3) * STG_BYTES;
#pragma unroll
        for (int k8 = 0; k8 < 16; k8 += 8) {
            uint32_t a0[4], a1[4];
            ldsm4(a0, st + a_off + (uint32_t)((warp_m * 32) * 20 + k8) * 4);
            ldsm4(a1, st + a_off + (uint32_t)((warp_m * 32 + 16) * 20 + k8) * 4);
#pragma unroll
            for (int ntp = 0; ntp < 4; ++ntp) {
                uint32_t bb[4];
                ldsm4(bb, st + b_off + (uint32_t)((warp_n * 64 + ntp * 16) * 20 + k8) * 4);
                mma1688(acc[0][2 * ntp],     a0, bb[0], bb[1]);
                mma1688(acc[1][2 * ntp],     a1, bb[0], bb[1]);
                mma1688(acc[0][2 * ntp + 1], a0, bb[2], bb[3]);
                mma1688(acc[1][2 * ntp + 1], a1, bb[2], bb[3]);
            }
        }
    }

    int lr = lane >> 2, lk = lane & 3;
    // epilogue (mode 0: round to tf32 for attention consumers; mode 1: gate)
#pragma unroll
    for (int mt = 0; mt < 2; ++mt) {
        int r = row0 + warp_m * 32 + mt * 16 + lr;
        int gb = (r >> 11) * H3_ + 2 * H_;
#pragma unroll
        for (int nt = 0; nt < 8; ++nt) {
            int c = col0 + warp_n * 64 + nt * 8 + lk * 2;
            float2 v0 = make_float2(acc[mt][nt][0], acc[mt][nt][1]);
            float2 v1 = make_float2(acc[mt][nt][2], acc[mt][nt][3]);
            if (mode) {
                float gx = g_mod[gb + c], gy = g_mod[gb + c + 1];
                v0.x *= gx; v0.y *= gy;
                v1.x *= gx; v1.y *= gy;
            } else {
                v0.x = to_tf32(v0.x); v0.y = to_tf32(v0.y);
                v1.x = to_tf32(v1.x); v1.y = to_tf32(v1.y);
            }
            *(float2*)(C + (size_t)r * N + c) = v0;
            *(float2*)(C + (size_t)(r + 8) * N + c) = v1;
        }
    }
}

// ============================================================
// 4) per-head QK layernorm + RoPE, in place on g_qkv
//    q gets 0.125*log2(e) folded in (softmax uses exp2); outputs tf32-rounded
// ============================================================
__global__ void __launch_bounds__(256) qknorm_rope_kernel(const float* __restrict__ freqs,
                                                          const float* __restrict__ qn_w,
                                                          const float* __restrict__ kn_w) {
    int row = blockIdx.x;
    int s = row & (S_ - 1);
    int warp = threadIdx.x >> 5;
    int lane = threadIdx.x & 31;

    float f0 = freqs[(s * 32 + lane) * 2 + 0];
    float f1 = freqs[(s * 32 + lane) * 2 + 1];

    for (int task = warp; task < 32; task += 8) {
        int type = task >> 4;
        int head = task & 15;
        size_t base = (size_t)row * H3_ + type * H_ + head * HD_;
        float v0 = g_qkv[base + lane * 2];
        float v1 = g_qkv[base + lane * 2 + 1];
        float sum = warp_sum(v0 + v1);
        float sq  = warp_sum(v0 * v0 + v1 * v1);
        float mean = sum * (1.f / 64.f);
        float var  = sq * (1.f / 64.f) - mean * mean;
        float rstd = rsqrtf(var + 1e-5f);
        const float* w = type ? kn_w : qn_w;
        float n0 = (v0 - mean) * rstd * w[lane * 2];
        float n1 = (v1 - mean) * rstd * w[lane * 2 + 1];
        float r0 = n0 * f0 - n1 * f1;
        float r1 = n1 * f0 + n0 * f1;
        float qs = type ? 1.f : (0.125f * 1.44269504088896340736f);
        g_qkv[base + lane * 2]     = to_tf32(r0 * qs);
        g_qkv[base + lane * 2 + 1] = to_tf32(r1 * qs);
    }
}

// ============================================================
// 5) flash attention (non-causal), tf32 mma.sync + ldmatrix, base-2 softmax
//    grid = (S/128, B*NH), 256 threads (8 warps x m16 q-rows)
// ============================================================
#define KS_ 68
#define VS_ 72
#define VT_S 68
#define PS_ 68
#define OFF_VB (2 * 64 * KS_)            // 8704
#define OFF_VT (OFF_VB + 2 * 64 * VS_)   // 17920
#define OFF_P  (OFF_VT + 64 * VT_S)      // 22272
#define ATT_SMEM ((OFF_P + 8 * 16 * PS_) * 4)   // 123904 bytes

__device__ __forceinline__ void attn_load_kv(uint32_t sb, const float* gkv, int t, int tid) {
    int s = t & 1;
    int r = tid >> 2;                 // 0..63 (key within tile)
    int cc = (tid & 3) * 16;          // dim chunk
    const float* kg = gkv + (size_t)(t * 64 + r) * H3_ + cc;
    const float* vg = kg + H_;
    uint32_t kd = sb + (uint32_t)(s * 64 * KS_ + r * KS_ + cc) * 4;
    uint32_t vd = sb + (uint32_t)(OFF_VB + s * 64 * VS_ + r * VS_ + cc) * 4;
#pragma unroll
    for (int i = 0; i < 4; ++i) {
        cp_async16(kd + i * 16, kg + i * 4);
        cp_async16(vd + i * 16, vg + i * 4);
    }
    asm volatile("cp.async.commit_group;" ::: "memory");
}

__global__ void __launch_bounds__(256, 1) attn_mma_kernel() {
    extern __shared__ float sm[];
    uint32_t sb = cvta_smem(sm);

    int tid = threadIdx.x, wid = tid >> 5, lane = tid & 31;
    int lr = lane >> 2, lk = lane & 3;
    int sub = lane & 7, mi = lane >> 3;
    int q0 = blockIdx.x << 7;
    int b = blockIdx.y >> 4, head = blockIdx.y & 15;

    const float* gkv = g_qkv + (size_t)b * S_ * H3_ + H_ + head * HD_;  // K base (V = +H_)

    // per-lane LDSM offsets (bytes)
    uint32_t k_loff = (uint32_t)(sub * KS_ + (mi >> 1) * 8 + (mi & 1) * 4) * 4;
    uint32_t vt_loff = (uint32_t)(((mi >> 1) * 8 + sub) * VT_S + (mi & 1) * 4) * 4;
    uint32_t p_loff = (uint32_t)(((mi & 1) * 8 + sub) * PS_ + (mi >> 1) * 4) * 4;

    // Q fragments (registers for the whole kernel; pre-scaled & tf32)
    uint32_t qa[8][4];
    {
        const float* Qb = g_qkv + (size_t)(b * S_ + q0 + wid * 16) * H3_ + head * HD_;
#pragma unroll
        for (int ks = 0; ks < 8; ++ks) {
            qa[ks][0] = __float_as_uint(Qb[(size_t)lr * H3_ + ks * 8 + lk]);
            qa[ks][1] = __float_as_uint(Qb[(size_t)(lr + 8) * H3_ + ks * 8 + lk]);
            qa[ks][2] = __float_as_uint(Qb[(size_t)lr * H3_ + ks * 8 + lk + 4]);
            qa[ks][3] = __float_as_uint(Qb[(size_t)(lr + 8) * H3_ + ks * 8 + lk + 4]);
        }
    }

    float m0 = -1e30f, m1 = -1e30f, l0 = 0.f, l1 = 0.f;
    float o[8][4];
#pragma unroll
    for (int nt = 0; nt < 8; ++nt)
#pragma unroll
        for (int q = 0; q < 4; ++q) o[nt][q] = 0.f;

    float* Pw = sm + OFF_P + wid * 16 * PS_;
    uint32_t Pwb = sb + (uint32_t)(OFF_P + wid * 16 * PS_) * 4;
    uint32_t VTb = sb + (uint32_t)OFF_VT * 4;

    attn_load_kv(sb, gkv, 0, tid);

    for (int t = 0; t < 32; ++t) {
        asm volatile("cp.async.wait_group 0;" ::: "memory");   // tile t resident
        __syncthreads();   // visible to all; prev iter's reads of buffer (t+1)&1 done
        if (t < 31) attn_load_kv(sb, gkv, t + 1, tid);

        // ---- transpose V tile: Vbuf[key][dim] -> VT[dim][key] ----
        {
            int key = tid & 63, dbase = (tid >> 6) * 16;
            const float* src = sm + OFF_VB + (t & 1) * 64 * VS_ + key * VS_ + dbase;
            float4 va = ((const float4*)src)[0];
            float4 vb4 = ((const float4*)src)[1];
            float4 vc = ((const float4*)src)[2];
            float4 vd = ((const float4*)src)[3];
            float vv[16] = {va.x, va.y, va.z, va.w, vb4.x, vb4.y, vb4.z, vb4.w,
                            vc.x, vc.y, vc.z, vc.w, vd.x, vd.y, vd.z, vd.w};
            float* vt = sm + OFF_VT;
#pragma unroll
            for (int d = 0; d < 16; ++d) vt[(dbase + d) * VT_S + key] = vv[d];
        }

        uint32_t Kst = sb + (uint32_t)((t & 1) * 64 * KS_) * 4;

        // ---- scores = Q @ K^T (pre-scaled, base-2 domain) ----
        float sc[8][4];
#pragma unroll
        for (int nt = 0; nt < 8; ++nt) {
            uint32_t kb[16];
#pragma unroll
            for (int p = 0; p < 4; ++p)
                ldsm4(kb + 4 * p, Kst + k_loff + (uint32_t)(nt * 8 * KS_ + p * 16) * 4);
#pragma unroll
            for (int q = 0; q < 4; ++q) sc[nt][q] = 0.f;
#pragma unroll
            for (int ks = 0; ks < 8; ++ks)
                mma1688(sc[nt], qa[ks], kb[2 * ks], kb[2 * ks + 1]);
        }

        // ---- online softmax, base 2 (rows lr, lr+8; quad lanes share a row) ----
        float tm0 = -1e30f, tm1 = -1e30f;
#pragma unroll
        for (int nt = 0; nt < 8; ++nt) {
            tm0 = fmaxf(tm0, fmaxf(sc[nt][0], sc[nt][1]));
            tm1 = fmaxf(tm1, fmaxf(sc[nt][2], sc[nt][3]));
        }
        tm0 = fmaxf(tm0, __shfl_xor_sync(0xffffffffu, tm0, 1));
        tm0 = fmaxf(tm0, __shfl_xor_sync(0xffffffffu, tm0, 2));
        tm1 = fmaxf(tm1, __shfl_xor_sync(0xffffffffu, tm1, 1));
        tm1 = fmaxf(tm1, __shfl_xor_sync(0xffffffffu, tm1, 2));
        float nm0 = fmaxf(m0, tm0), nm1 = fmaxf(m1, tm1);
        float a0 = exp2f(m0 - nm0), a1 = exp2f(m1 - nm1);
        m0 = nm0; m1 = nm1;

        float rs0 = 0.f, rs1 = 0.f;
#pragma unroll
        for (int nt = 0; nt < 8; ++nt) {
            float p0 = exp2f(sc[nt][0] - nm0);
            float p1 = exp2f(sc[nt][1] - nm0);
            float p2 = exp2f(sc[nt][2] - nm1);
            float p3 = exp2f(sc[nt][3] - nm1);
            rs0 += p0 + p1;
            rs1 += p2 + p3;
            *(float2*)(Pw + lr * PS_ + nt * 8 + lk * 2) =
                make_float2(to_tf32(p0), to_tf32(p1));
            *(float2*)(Pw + (lr + 8) * PS_ + nt * 8 + lk * 2) =
                make_float2(to_tf32(p2), to_tf32(p3));
        }
        rs0 += __shfl_xor_sync(0xffffffffu, rs0, 1);
        rs0 += __shfl_xor_sync(0xffffffffu, rs0, 2);
        rs1 += __shfl_xor_sync(0xffffffffu, rs1, 1);
        rs1 += __shfl_xor_sync(0xffffffffu, rs1, 2);
        l0 = l0 * a0 + rs0;
        l1 = l1 * a1 + rs1;
#pragma unroll
        for (int nt = 0; nt < 8; ++nt) {
            o[nt][0] *= a0; o[nt][1] *= a0;
            o[nt][2] *= a1; o[nt][3] *= a1;
        }
        __syncthreads();   // VT transposed + visible

        // ---- O += P @ V  (P A-frags + VT B-frags via LDSM) ----
#pragma unroll
        for (int ks = 0; ks < 8; ++ks) {
            uint32_t pa[4];
            ldsm4(pa, Pwb + p_loff + (uint32_t)(ks * 8) * 4);
#pragma unroll
            for (int ntp = 0; ntp < 4; ++ntp) {
                uint32_t vb[4];
                ldsm4(vb, VTb + vt_loff + (uint32_t)(ntp * 16 * VT_S + ks * 8) * 4);
                mma1688(o[2 * ntp],     pa, vb[0], vb[1]);
                mma1688(o[2 * ntp + 1], pa, vb[2], vb[3]);
            }
        }
    }

    float inv0 = 1.f / l0, inv1 = 1.f / l1;
    int r = b * S_ + q0 + wid * 16 + lr;
    float* ob = g_o + (size_t)r * H_ + head * HD_;
#pragma unroll
    for (int nt = 0; nt < 8; ++nt) {
        *(float2*)(ob + nt * 8 + lk * 2) =
            make_float2(to_tf32(o[nt][0] * inv0), to_tf32(o[nt][1] * inv0));
        *(float2*)(ob + (size_t)8 * H_ + nt * 8 + lk * 2) =
            make_float2(to_tf32(o[nt][2] * inv1), to_tf32(o[nt][3] * inv1));
    }
}

// ============================================================
extern "C" void kernel_launch(void* const* d_in, const int* in_sizes, int n_in,
                              void* d_out, int out_size) {
    (void)in_sizes; (void)n_in; (void)out_size;
    const float* x     = (const float*)d_in[0];
    const float* ada   = (const float*)d_in[1];
    const float* freqs = (const float*)d_in[2];
    const float* w_qkv = (const float*)d_in[3];
    const float* w_o   = (const float*)d_in[4];
    const float* ln_w  = (const float*)d_in[5];
    const float* mod_w = (const float*)d_in[6];
    const float* mod_b = (const float*)d_in[7];
    const float* qn_w  = (const float*)d_in[8];
    const float* kn_w  = (const float*)d_in[9];
    float* out = (float*)d_out;

    const int SMEM_DYN = 4 * STG_BYTES;   // 81920 bytes
    cudaFuncSetAttribute(tc_gemm, cudaFuncAttributeMaxDynamicSharedMemorySize, SMEM_DYN);
    cudaFuncSetAttribute(attn_mma_kernel, cudaFuncAttributeMaxDynamicSharedMemorySize, ATT_SMEM);

    mod_kernel<<<768, 256>>>(ada, mod_w, mod_b);
    round_w_kernel<<<4096, 256>>>(w_qkv, w_o);
    ln_mod_kernel<<<R_, 256>>>(x, ln_w);
    tc_gemm<<<dim3(H3_ / 128, R_ / 128), 256, SMEM_DYN>>>(nullptr, H3_, 0);
    qknorm_rope_kernel<<<R_, 256>>>(freqs, qn_w, kn_w);
    attn_mma_kernel<<<dim3(S_ / 128, B_ * NH_), 256, ATT_SMEM>>>();
    tc_gemm<<<dim3(H_ / 128, R_ / 128), 256, SMEM_DYN>>>(out, H_, 1);
}